// round 6
// baseline (speedup 1.0000x reference)
#include <cuda_runtime.h>
#include <cuda_fp16.h>
#include <stdint.h>

#define B_  4
#define H_  16
#define S_  2048
#define DK_ 64
#define MT  128     // q rows per CTA
#define KT  64      // k rows per tile
#define NTHR 256    // 8 warps, 16 q-rows each
#define ROWH 72     // padded row pitch in halves (144B)

// ---------------- static scratch ----------------
#define NEL ((size_t)B_ * H_ * S_ * DK_)            // 8.4M
__device__ __align__(16) __half g_qh[NEL], g_ql[NEL];
__device__ __align__(16) __half g_kh[NEL], g_kl[NEL];
__device__ __align__(16) __half g_vh[NEL], g_vl[NEL];
__device__ __align__(16) __half g_escr[(size_t)B_ * H_ * S_ * S_];     // 512MB unnormalized e (fp16)
__device__ __align__(16) unsigned long long g_maskbits[(size_t)B_ * S_ * (S_ / 64)];

// ---------------- helpers ----------------
__device__ __forceinline__ uint32_t pack2(float a, float b) {
    __half2 h = __floats2half2_rn(a, b);
    return *reinterpret_cast<uint32_t*>(&h);
}
__device__ __forceinline__ float2 unpack2(uint32_t u) {
    __half2 h = *reinterpret_cast<__half2*>(&u);
    return __half22float2(h);
}
__device__ __forceinline__ void cp16(uint32_t dst, const void* src) {
    asm volatile("cp.async.cg.shared.global [%0], [%1], 16;" :: "r"(dst), "l"(src));
}
#define CP_COMMIT() asm volatile("cp.async.commit_group;" ::: "memory")
#define CP_WAIT1()  asm volatile("cp.async.wait_group 1;" ::: "memory")

#define LDSM4(r, a) \
    asm volatile("ldmatrix.sync.aligned.m8n8.x4.shared.b16 {%0,%1,%2,%3}, [%4];" \
        : "=r"((r)[0]), "=r"((r)[1]), "=r"((r)[2]), "=r"((r)[3]) : "r"(a))
#define LDSM4T(r, a) \
    asm volatile("ldmatrix.sync.aligned.m8n8.x4.trans.shared.b16 {%0,%1,%2,%3}, [%4];" \
        : "=r"((r)[0]), "=r"((r)[1]), "=r"((r)[2]), "=r"((r)[3]) : "r"(a))
#define MMA16816(c, a, b0, b1) \
    asm volatile("mma.sync.aligned.m16n8k16.row.col.f32.f16.f16.f32 " \
        "{%0,%1,%2,%3},{%4,%5,%6,%7},{%8,%9},{%0,%1,%2,%3};" \
        : "+f"((c)[0]), "+f"((c)[1]), "+f"((c)[2]), "+f"((c)[3]) \
        : "r"((a)[0]), "r"((a)[1]), "r"((a)[2]), "r"((a)[3]), "r"(b0), "r"(b1))

// smem layout in halves: Qh | Ql | 2 x {Kh, Kl, Vh, Vl} ; then zr[128] floats
#define OFF_QH 0
#define OFF_QL 9216
#define OFF_BUF 18432
#define BUF_SZ  18432      // per buffer: 4 arrays x 64*72 halves
#define OFF_ZR  ((OFF_BUF + 2 * BUF_SZ) * 2)          // byte offset
#define SMEM_BYTES (OFF_ZR + MT * 4)                  // 111104 B

// ================= prep: split QKV to fp16 hi/lo + bit-pack mask =================
__global__ void prep_kernel(const float4* __restrict__ Q, const float4* __restrict__ K,
                            const float4* __restrict__ V, const unsigned int* __restrict__ m)
{
    const int tid = threadIdx.x;
    if (blockIdx.x < 512) {
        const size_t n = NEL / 4;
        for (size_t i = (size_t)blockIdx.x * 256 + tid; i < n; i += 512 * 256) {
            float4 q = Q[i];
            q.x *= 0.125f; q.y *= 0.125f; q.z *= 0.125f; q.w *= 0.125f;
            uint32_t h0 = pack2(q.x, q.y), h1 = pack2(q.z, q.w);
            float2 a0 = unpack2(h0), a1 = unpack2(h1);
            *(uint2*)(g_qh + 4 * i) = make_uint2(h0, h1);
            *(uint2*)(g_ql + 4 * i) = make_uint2(pack2(q.x - a0.x, q.y - a0.y),
                                                 pack2(q.z - a1.x, q.w - a1.y));
            float4 k = K[i];
            h0 = pack2(k.x, k.y); h1 = pack2(k.z, k.w);
            a0 = unpack2(h0); a1 = unpack2(h1);
            *(uint2*)(g_kh + 4 * i) = make_uint2(h0, h1);
            *(uint2*)(g_kl + 4 * i) = make_uint2(pack2(k.x - a0.x, k.y - a0.y),
                                                 pack2(k.z - a1.x, k.w - a1.y));
            float4 v = V[i];
            h0 = pack2(v.x, v.y); h1 = pack2(v.z, v.w);
            a0 = unpack2(h0); a1 = unpack2(h1);
            *(uint2*)(g_vh + 4 * i) = make_uint2(h0, h1);
            *(uint2*)(g_vl + 4 * i) = make_uint2(pack2(v.x - a0.x, v.y - a0.y),
                                                 pack2(v.z - a1.x, v.w - a1.y));
        }
    } else {
        // classify mask dtype (word 0/1, float 0/1.0f, or packed bytes), then bit-pack
        __shared__ int bad01_s, isfloat_s;
        if (tid == 0) { bad01_s = 0; isfloat_s = 1; }
        __syncthreads();
        int bad01 = 0;
        for (int i = tid; i < 4096; i += 256)
            if (m[i] > 1u) bad01 = 1;
        if (bad01) atomicExch(&bad01_s, 1);
        __syncthreads();
        if (bad01_s) {
            int notf = 0;
            for (int i = tid; i < 4096; i += 256) {
                unsigned v = m[i];
                if (v != 0u && v != 0x3F800000u) notf = 1;
            }
            if (notf) atomicExch(&isfloat_s, 0);
        }
        __syncthreads();
        const bool bytemask = bad01_s && !isfloat_s;
        const size_t n = (size_t)B_ * S_ * (S_ / 64);
        for (size_t i = (size_t)(blockIdx.x - 512) * 256 + tid; i < n; i += 512 * 256) {
            unsigned long long bits = 0ull;
            if (bytemask) {
                const uint4* p = (const uint4*)((const unsigned char*)m + i * 64);
                #pragma unroll
                for (int j = 0; j < 4; j++) {
                    uint4 v = p[j];
                    unsigned w[4] = {v.x, v.y, v.z, v.w};
                    #pragma unroll
                    for (int q = 0; q < 4; q++)
                        #pragma unroll
                        for (int bb = 0; bb < 4; bb++)
                            bits |= (unsigned long long)(((w[q] >> (8 * bb)) & 0xffu) == 0u)
                                    << (j * 16 + q * 4 + bb);
                }
            } else {
                const uint4* p = (const uint4*)m + i * 16;
                #pragma unroll
                for (int j = 0; j < 16; j++) {
                    uint4 v = p[j];
                    bits |= ((unsigned long long)(v.x == 0u) << (4 * j))
                          | ((unsigned long long)(v.y == 0u) << (4 * j + 1))
                          | ((unsigned long long)(v.z == 0u) << (4 * j + 2))
                          | ((unsigned long long)(v.w == 0u) << (4 * j + 3));
                }
            }
            g_maskbits[i] = bits;
        }
    }
}

// ================= fused flash + normalize =================
__global__ void __launch_bounds__(NTHR, 1)
attn_main(float* __restrict__ ctx_out, float* __restrict__ attn_out)
{
    extern __shared__ __half shm[];
    float* zr = (float*)((char*)shm + OFF_ZR);
    const uint32_t sb = (uint32_t)__cvta_generic_to_shared(shm);

    const int tid = threadIdx.x, wid = tid >> 5, lane = tid & 31;
    const int r = lane >> 2, qc = lane & 3;
    const int m0 = 16 * wid;
    const int arow = lane & 15;
    const int akof = (lane >> 4) << 3;
    const int nlaneK = (lane & 7) + ((lane & 16) >> 1);
    const int klaneK = lane & 8;
    const int klaneV = lane & 15;
    const int nlaneV = (lane >> 4) << 3;

    const int q0 = blockIdx.x * MT;
    const size_t bh = (size_t)blockIdx.z * H_ + blockIdx.y;
    const size_t kvbase = bh * S_ * DK_;

    const int gr0 = q0 + m0 + r, gr1 = gr0 + 8;
    const unsigned long long* mbp = g_maskbits + (size_t)blockIdx.z * S_ * (S_ / 64);
    const __half* kvsrc[4] = {g_kh + kvbase, g_kl + kvbase, g_vh + kvbase, g_vl + kvbase};
    __half* ep0 = g_escr + (bh * S_ + gr0) * (size_t)S_;
    __half* ep1 = g_escr + (bh * S_ + gr1) * (size_t)S_;

    // ---- issue Q + tile 0 loads ----
    {
        const size_t qrow0 = bh * S_ + q0;
        #pragma unroll
        for (int it = 0; it < 8; it++) {
            int i = tid + it * NTHR;           // 0..2047: Qh then Ql, 128 rows x 8 chunks
            int arr = i >> 10, rem = i & 1023, row = rem >> 3, c8 = rem & 7;
            const __half* src = (arr ? g_ql : g_qh) + (qrow0 + row) * DK_ + c8 * 8;
            cp16(sb + ((arr ? OFF_QL : OFF_QH) + row * ROWH + c8 * 8) * 2, src);
        }
        #pragma unroll
        for (int it = 0; it < 8; it++) {
            int i = tid + it * NTHR;           // 0..2047: 4 arrays x 64 rows x 8 chunks
            int arr = i >> 9, rem = i & 511, row = rem >> 3, c8 = rem & 7;
            cp16(sb + (OFF_BUF + arr * 4608 + row * ROWH + c8 * 8) * 2,
                 kvsrc[arr] + (size_t)row * DK_ + c8 * 8);
        }
        CP_COMMIT();
    }

    float ctx[8][4];
    #pragma unroll
    for (int j = 0; j < 8; j++)
        #pragma unroll
        for (int k = 0; k < 4; k++) ctx[j][k] = 0.f;
    float z0 = 0.f, z1 = 0.f;

    // Q fragments (loaded after first wait)
    uint32_t qhi[4][4], qlo[4][4];
    bool qloaded = false;

    for (int kt = 0; kt < S_ / KT; kt++) {
        if (kt < S_ / KT - 1) {
            const int nb = OFF_BUF + ((kt + 1) & 1) * BUF_SZ;
            const size_t rbase = (size_t)(kt + 1) * KT * DK_;
            #pragma unroll
            for (int it = 0; it < 8; it++) {
                int i = tid + it * NTHR;
                int arr = i >> 9, rem = i & 511, row = rem >> 3, c8 = rem & 7;
                cp16(sb + (nb + arr * 4608 + row * ROWH + c8 * 8) * 2,
                     kvsrc[arr] + rbase + (size_t)row * DK_ + c8 * 8);
            }
        }
        CP_COMMIT();
        CP_WAIT1();
        __syncthreads();

        if (!qloaded) {
            qloaded = true;
            #pragma unroll
            for (int s = 0; s < 4; s++) {
                const uint32_t qa = (uint32_t)((m0 + arow) * ROWH + 16 * s + akof) * 2;
                LDSM4(qhi[s], sb + OFF_QH * 2 + qa);
                LDSM4(qlo[s], sb + OFF_QL * 2 + qa);
            }
        }

        const int bufh = OFF_BUF + (kt & 1) * BUF_SZ;
        const uint32_t kh = sb + bufh * 2;
        const uint32_t kl = sb + (bufh + 4608) * 2;
        const uint32_t vh = sb + (bufh + 9216) * 2;
        const uint32_t vl = sb + (bufh + 13824) * 2;

        // ---- GEMM1: 16x64 scores = Qhi*Khi + Qlo*Khi + Qhi*Klo ----
        float c[8][4];
        #pragma unroll
        for (int j = 0; j < 8; j++)
            #pragma unroll
            for (int k = 0; k < 4; k++) c[j][k] = 0.f;

        #pragma unroll
        for (int s = 0; s < 4; s++) {
            #pragma unroll
            for (int Jp = 0; Jp < 4; Jp++) {
                const uint32_t bo = (uint32_t)((16 * Jp + nlaneK) * ROWH + 16 * s + klaneK) * 2;
                uint32_t kb[4];
                LDSM4(kb, kh + bo);
                MMA16816(c[2 * Jp],     qhi[s], kb[0], kb[1]);
                MMA16816(c[2 * Jp + 1], qhi[s], kb[2], kb[3]);
                MMA16816(c[2 * Jp],     qlo[s], kb[0], kb[1]);
                MMA16816(c[2 * Jp + 1], qlo[s], kb[2], kb[3]);
                LDSM4(kb, kl + bo);
                MMA16816(c[2 * Jp],     qhi[s], kb[0], kb[1]);
                MMA16816(c[2 * Jp + 1], qhi[s], kb[2], kb[3]);
            }
        }

        // ---- elt + GEMM2 interleaved per k16-chunk ----
        const unsigned long long mw0 = mbp[(size_t)gr0 * (S_ / 64) + kt];
        const unsigned long long mw1 = mbp[(size_t)gr1 * (S_ / 64) + kt];

        #pragma unroll
        for (int s = 0; s < 4; s++) {
            uint32_t phi[4], plo[4];
            #pragma unroll
            for (int jj = 0; jj < 2; jj++) {
                const int j = 2 * s + jj;
                const int col = 8 * j + 2 * qc;
                float e00 = ((mw0 >> col) & 1ull)       ? __expf(c[j][0]) : 0.f;
                float e01 = ((mw0 >> (col + 1)) & 1ull) ? __expf(c[j][1]) : 0.f;
                float e10 = ((mw1 >> col) & 1ull)       ? __expf(c[j][2]) : 0.f;
                float e11 = ((mw1 >> (col + 1)) & 1ull) ? __expf(c[j][3]) : 0.f;
                z0 += e00 + e01; z1 += e10 + e11;
                uint32_t h0 = pack2(e00, e01), h1 = pack2(e10, e11);
                __stcg((uint32_t*)((char*)ep0 + (size_t)(kt * KT + col) * 2), h0);
                __stcg((uint32_t*)((char*)ep1 + (size_t)(kt * KT + col) * 2), h1);
                float2 a0 = unpack2(h0), a1 = unpack2(h1);
                phi[2 * jj] = h0; phi[2 * jj + 1] = h1;
                plo[2 * jj] = pack2(e00 - a0.x, e01 - a0.y);
                plo[2 * jj + 1] = pack2(e10 - a1.x, e11 - a1.y);
            }
            #pragma unroll
            for (int P = 0; P < 4; P++) {
                const uint32_t vo = (uint32_t)((16 * s + klaneV) * ROWH + 16 * P + nlaneV) * 2;
                uint32_t vb[4];
                LDSM4T(vb, vh + vo);
                MMA16816(ctx[2 * P],     phi, vb[0], vb[1]);
                MMA16816(ctx[2 * P + 1], phi, vb[2], vb[3]);
                MMA16816(ctx[2 * P],     plo, vb[0], vb[1]);
                MMA16816(ctx[2 * P + 1], plo, vb[2], vb[3]);
                LDSM4T(vb, vl + vo);
                MMA16816(ctx[2 * P],     phi, vb[0], vb[1]);
                MMA16816(ctx[2 * P + 1], phi, vb[2], vb[3]);
            }
        }
        __syncthreads();
    }

    // ---- zinv + ctx epilogue ----
    z0 += __shfl_xor_sync(0xffffffffu, z0, 1);
    z0 += __shfl_xor_sync(0xffffffffu, z0, 2);
    z1 += __shfl_xor_sync(0xffffffffu, z1, 1);
    z1 += __shfl_xor_sync(0xffffffffu, z1, 2);
    const float zinv0 = 1.0f / z0, zinv1 = 1.0f / z1;
    if (qc == 0) { zr[m0 + r] = zinv0; zr[m0 + r + 8] = zinv1; }

    float* crow0 = ctx_out + (bh * S_ + gr0) * DK_;
    float* crow1 = ctx_out + (bh * S_ + gr1) * DK_;
    #pragma unroll
    for (int j = 0; j < 8; j++) {
        const int col = 8 * j + 2 * qc;
        __stwt((float2*)(crow0 + col), make_float2(ctx[j][0] * zinv0, ctx[j][1] * zinv0));
        __stwt((float2*)(crow1 + col), make_float2(ctx[j][2] * zinv1, ctx[j][3] * zinv1));
    }

    // ---- fused normalize: e (fp16, L2-hot) -> attn (fp32), this CTA's 128 rows ----
    __syncthreads();   // zr visible + all e-stores of this CTA visible (cta-scope)
    const __half* eb = g_escr + (bh * S_ + q0) * (size_t)S_;
    float* ab = attn_out + (bh * S_ + q0) * (size_t)S_;
    #pragma unroll 2
    for (int row = 0; row < MT; row++) {
        const float zi = zr[row];
        uint4 v = __ldcs((const uint4*)(eb + (size_t)row * S_) + tid);
        float2 p0 = unpack2(v.x), p1 = unpack2(v.y), p2 = unpack2(v.z), p3 = unpack2(v.w);
        float4* a = (float4*)(ab + (size_t)row * S_) + 2 * tid;
        __stwt(a,     make_float4(p0.x * zi, p0.y * zi, p1.x * zi, p1.y * zi));
        __stwt(a + 1, make_float4(p2.x * zi, p2.y * zi, p3.x * zi, p3.y * zi));
    }
}

// ---------------- launch ----------------
extern "C" void kernel_launch(void* const* d_in, const int* in_sizes, int n_in,
                              void* d_out, int out_size) {
    (void)in_sizes; (void)n_in; (void)out_size;
    const float* Q = (const float*)d_in[0];
    const float* K = (const float*)d_in[1];
    const float* V = (const float*)d_in[2];
    const void*  mask = d_in[3];

    float* ctx_out  = (float*)d_out;
    float* attn_out = ctx_out + NEL;

    cudaFuncSetAttribute(attn_main, cudaFuncAttributeMaxDynamicSharedMemorySize, SMEM_BYTES);

    prep_kernel<<<1024, 256>>>((const float4*)Q, (const float4*)K, (const float4*)V,
                               (const unsigned int*)mask);
    dim3 grid(S_ / MT, H_, B_);
    attn_main<<<grid, NTHR, SMEM_BYTES>>>(ctx_out, attn_out);
}

// round 7
// speedup vs baseline: 1.5307x; 1.5307x over previous
#include <cuda_runtime.h>
#include <cuda_fp16.h>
#include <stdint.h>

#define B_  4
#define H_  16
#define S_  2048
#define DK_ 64
#define MT  128     // q rows per CTA
#define KT  64      // k rows per tile
#define NTHR 256    // 8 warps, 16 q-rows each
#define ROWH 72     // padded row pitch in halves (144B)

// ---------------- static scratch ----------------
#define NEL ((size_t)B_ * H_ * S_ * DK_)            // 8.4M
__device__ __align__(16) __half g_qh[NEL], g_ql[NEL];
__device__ __align__(16) __half g_kh[NEL];
__device__ __align__(16) __half g_vh[NEL];
__device__ __align__(16) __half g_escr[(size_t)B_ * H_ * S_ * S_];     // 512MB unnormalized e (fp16)
__device__ __align__(16) unsigned long long g_maskbits[(size_t)B_ * S_ * (S_ / 64)];
__device__ float g_zinv[B_ * H_ * S_];

// ---------------- helpers ----------------
__device__ __forceinline__ uint32_t pack2(float a, float b) {
    __half2 h = __floats2half2_rn(a, b);
    return *reinterpret_cast<uint32_t*>(&h);
}
__device__ __forceinline__ float2 unpack2(uint32_t u) {
    __half2 h = *reinterpret_cast<__half2*>(&u);
    return __half22float2(h);
}
__device__ __forceinline__ void cp16(uint32_t dst, const void* src) {
    asm volatile("cp.async.cg.shared.global [%0], [%1], 16;" :: "r"(dst), "l"(src));
}
#define CP_COMMIT() asm volatile("cp.async.commit_group;" ::: "memory")
#define CP_WAIT1()  asm volatile("cp.async.wait_group 1;" ::: "memory")

#define LDSM4(r, a) \
    asm volatile("ldmatrix.sync.aligned.m8n8.x4.shared.b16 {%0,%1,%2,%3}, [%4];" \
        : "=r"((r)[0]), "=r"((r)[1]), "=r"((r)[2]), "=r"((r)[3]) : "r"(a))
#define LDSM4T(r, a) \
    asm volatile("ldmatrix.sync.aligned.m8n8.x4.trans.shared.b16 {%0,%1,%2,%3}, [%4];" \
        : "=r"((r)[0]), "=r"((r)[1]), "=r"((r)[2]), "=r"((r)[3]) : "r"(a))
#define MMA16816(c, a, b0, b1) \
    asm volatile("mma.sync.aligned.m16n8k16.row.col.f32.f16.f16.f32 " \
        "{%0,%1,%2,%3},{%4,%5,%6,%7},{%8,%9},{%0,%1,%2,%3};" \
        : "+f"((c)[0]), "+f"((c)[1]), "+f"((c)[2]), "+f"((c)[3]) \
        : "r"((a)[0]), "r"((a)[1]), "r"((a)[2]), "r"((a)[3]), "r"(b0), "r"(b1))

// smem layout in halves: Qh | Ql | 2 x {Kh, Vh}
#define OFF_QH 0
#define OFF_QL 9216
#define OFF_BUF 18432
#define BUF_SZ  9216       // per buffer: 2 arrays x 64*72 halves
#define SMEM_BYTES ((OFF_BUF + 2 * BUF_SZ) * 2)    // 73728 B

// ================= prep: Q -> fp16 hi/lo (x0.125), K/V -> fp16 hi, mask -> bits ==========
__global__ void prep_kernel(const float4* __restrict__ Q, const float4* __restrict__ K,
                            const float4* __restrict__ V, const unsigned int* __restrict__ m)
{
    const int tid = threadIdx.x;
    if (blockIdx.x < 512) {
        const size_t n = NEL / 4;
        for (size_t i = (size_t)blockIdx.x * 256 + tid; i < n; i += 512 * 256) {
            float4 q = Q[i];
            q.x *= 0.125f; q.y *= 0.125f; q.z *= 0.125f; q.w *= 0.125f;
            uint32_t h0 = pack2(q.x, q.y), h1 = pack2(q.z, q.w);
            float2 a0 = unpack2(h0), a1 = unpack2(h1);
            *(uint2*)(g_qh + 4 * i) = make_uint2(h0, h1);
            *(uint2*)(g_ql + 4 * i) = make_uint2(pack2(q.x - a0.x, q.y - a0.y),
                                                 pack2(q.z - a1.x, q.w - a1.y));
            float4 k = K[i];
            *(uint2*)(g_kh + 4 * i) = make_uint2(pack2(k.x, k.y), pack2(k.z, k.w));
            float4 v = V[i];
            *(uint2*)(g_vh + 4 * i) = make_uint2(pack2(v.x, v.y), pack2(v.z, v.w));
        }
    } else {
        // classify mask dtype (word 0/1, float 0/1.0f, or packed bytes), then bit-pack
        __shared__ int bad01_s, isfloat_s;
        if (tid == 0) { bad01_s = 0; isfloat_s = 1; }
        __syncthreads();
        int bad01 = 0;
        for (int i = tid; i < 4096; i += 256)
            if (m[i] > 1u) bad01 = 1;
        if (bad01) atomicExch(&bad01_s, 1);
        __syncthreads();
        if (bad01_s) {
            int notf = 0;
            for (int i = tid; i < 4096; i += 256) {
                unsigned v = m[i];
                if (v != 0u && v != 0x3F800000u) notf = 1;
            }
            if (notf) atomicExch(&isfloat_s, 0);
        }
        __syncthreads();
        const bool bytemask = bad01_s && !isfloat_s;
        const size_t n = (size_t)B_ * S_ * (S_ / 64);
        for (size_t i = (size_t)(blockIdx.x - 512) * 256 + tid; i < n; i += 512 * 256) {
            unsigned long long bits = 0ull;
            if (bytemask) {
                const uint4* p = (const uint4*)((const unsigned char*)m + i * 64);
                #pragma unroll
                for (int j = 0; j < 4; j++) {
                    uint4 v = p[j];
                    unsigned w[4] = {v.x, v.y, v.z, v.w};
                    #pragma unroll
                    for (int q = 0; q < 4; q++)
                        #pragma unroll
                        for (int bb = 0; bb < 4; bb++)
                            bits |= (unsigned long long)(((w[q] >> (8 * bb)) & 0xffu) == 0u)
                                    << (j * 16 + q * 4 + bb);
                }
            } else {
                const uint4* p = (const uint4*)m + i * 16;
                #pragma unroll
                for (int j = 0; j < 16; j++) {
                    uint4 v = p[j];
                    bits |= ((unsigned long long)(v.x == 0u) << (4 * j))
                          | ((unsigned long long)(v.y == 0u) << (4 * j + 1))
                          | ((unsigned long long)(v.z == 0u) << (4 * j + 2))
                          | ((unsigned long long)(v.w == 0u) << (4 * j + 3));
                }
            }
            g_maskbits[i] = bits;
        }
    }
}

// ================= mainloop: flash -> ctx + zinv + e.fp16 scratch =================
__global__ void __launch_bounds__(NTHR, 1)
attn_main(float* __restrict__ ctx_out)
{
    extern __shared__ __half shm[];
    const uint32_t sb = (uint32_t)__cvta_generic_to_shared(shm);

    const int tid = threadIdx.x, wid = tid >> 5, lane = tid & 31;
    const int r = lane >> 2, qc = lane & 3;
    const int m0 = 16 * wid;
    const int arow = lane & 15;
    const int akof = (lane >> 4) << 3;
    const int nlaneK = (lane & 7) + ((lane & 16) >> 1);
    const int klaneK = lane & 8;
    const int klaneV = lane & 15;
    const int nlaneV = (lane >> 4) << 3;

    const int q0 = blockIdx.x * MT;
    const size_t bh = (size_t)blockIdx.z * H_ + blockIdx.y;
    const size_t kvbase = bh * S_ * DK_;

    const int gr0 = q0 + m0 + r, gr1 = gr0 + 8;
    const unsigned long long* mbp = g_maskbits + (size_t)blockIdx.z * S_ * (S_ / 64);
    const __half* kvsrc[2] = {g_kh + kvbase, g_vh + kvbase};
    __half* ep0 = g_escr + (bh * S_ + gr0) * (size_t)S_;
    __half* ep1 = g_escr + (bh * S_ + gr1) * (size_t)S_;

    // ---- issue Q + tile 0 loads ----
    {
        const size_t qrow0 = bh * S_ + q0;
        #pragma unroll
        for (int it = 0; it < 8; it++) {
            int i = tid + it * NTHR;           // 0..2047: Qh then Ql, 128 rows x 8 chunks
            int arr = i >> 10, rem = i & 1023, row = rem >> 3, c8 = rem & 7;
            const __half* src = (arr ? g_ql : g_qh) + (qrow0 + row) * DK_ + c8 * 8;
            cp16(sb + ((arr ? OFF_QL : OFF_QH) + row * ROWH + c8 * 8) * 2, src);
        }
        #pragma unroll
        for (int it = 0; it < 4; it++) {
            int i = tid + it * NTHR;           // 0..1023: 2 arrays x 64 rows x 8 chunks
            int arr = i >> 9, rem = i & 511, row = rem >> 3, c8 = rem & 7;
            cp16(sb + (OFF_BUF + arr * 4608 + row * ROWH + c8 * 8) * 2,
                 kvsrc[arr] + (size_t)row * DK_ + c8 * 8);
        }
        CP_COMMIT();
    }

    float ctx[8][4];
    #pragma unroll
    for (int j = 0; j < 8; j++)
        #pragma unroll
        for (int k = 0; k < 4; k++) ctx[j][k] = 0.f;
    float z0 = 0.f, z1 = 0.f;

    uint32_t qhi[4][4], qlo[4][4];
    bool qloaded = false;

    for (int kt = 0; kt < S_ / KT; kt++) {
        if (kt < S_ / KT - 1) {
            const int nb = OFF_BUF + ((kt + 1) & 1) * BUF_SZ;
            const size_t rbase = (size_t)(kt + 1) * KT * DK_;
            #pragma unroll
            for (int it = 0; it < 4; it++) {
                int i = tid + it * NTHR;
                int arr = i >> 9, rem = i & 511, row = rem >> 3, c8 = rem & 7;
                cp16(sb + (nb + arr * 4608 + row * ROWH + c8 * 8) * 2,
                     kvsrc[arr] + rbase + (size_t)row * DK_ + c8 * 8);
            }
        }
        CP_COMMIT();
        CP_WAIT1();
        __syncthreads();

        if (!qloaded) {
            qloaded = true;
            #pragma unroll
            for (int s = 0; s < 4; s++) {
                const uint32_t qa = (uint32_t)((m0 + arow) * ROWH + 16 * s + akof) * 2;
                LDSM4(qhi[s], sb + OFF_QH * 2 + qa);
                LDSM4(qlo[s], sb + OFF_QL * 2 + qa);
            }
        }

        const int bufh = OFF_BUF + (kt & 1) * BUF_SZ;
        const uint32_t kh = sb + bufh * 2;
        const uint32_t vh = sb + (bufh + 4608) * 2;

        // ---- GEMM1: 16x64 scores = (Qhi + Qlo) * Khi ----
        float c[8][4];
        #pragma unroll
        for (int j = 0; j < 8; j++)
            #pragma unroll
            for (int k = 0; k < 4; k++) c[j][k] = 0.f;

        #pragma unroll
        for (int s = 0; s < 4; s++) {
            #pragma unroll
            for (int Jp = 0; Jp < 4; Jp++) {
                const uint32_t bo = (uint32_t)((16 * Jp + nlaneK) * ROWH + 16 * s + klaneK) * 2;
                uint32_t kb[4];
                LDSM4(kb, kh + bo);
                MMA16816(c[2 * Jp],     qhi[s], kb[0], kb[1]);
                MMA16816(c[2 * Jp + 1], qhi[s], kb[2], kb[3]);
                MMA16816(c[2 * Jp],     qlo[s], kb[0], kb[1]);
                MMA16816(c[2 * Jp + 1], qlo[s], kb[2], kb[3]);
            }
        }

        // ---- elt + GEMM2 interleaved per k16-chunk ----
        const unsigned long long mw0 = mbp[(size_t)gr0 * (S_ / 64) + kt];
        const unsigned long long mw1 = mbp[(size_t)gr1 * (S_ / 64) + kt];

        #pragma unroll
        for (int s = 0; s < 4; s++) {
            uint32_t phi[4], plo[4];
            #pragma unroll
            for (int jj = 0; jj < 2; jj++) {
                const int j = 2 * s + jj;
                const int col = 8 * j + 2 * qc;
                float e00 = ((mw0 >> col) & 1ull)       ? __expf(c[j][0]) : 0.f;
                float e01 = ((mw0 >> (col + 1)) & 1ull) ? __expf(c[j][1]) : 0.f;
                float e10 = ((mw1 >> col) & 1ull)       ? __expf(c[j][2]) : 0.f;
                float e11 = ((mw1 >> (col + 1)) & 1ull) ? __expf(c[j][3]) : 0.f;
                z0 += e00 + e01; z1 += e10 + e11;
                uint32_t h0 = pack2(e00, e01), h1 = pack2(e10, e11);
                __stwt((uint32_t*)((char*)ep0 + (size_t)(kt * KT + col) * 2), h0);
                __stwt((uint32_t*)((char*)ep1 + (size_t)(kt * KT + col) * 2), h1);
                float2 a0 = unpack2(h0), a1 = unpack2(h1);
                phi[2 * jj] = h0; phi[2 * jj + 1] = h1;
                plo[2 * jj] = pack2(e00 - a0.x, e01 - a0.y);
                plo[2 * jj + 1] = pack2(e10 - a1.x, e11 - a1.y);
            }
            #pragma unroll
            for (int P = 0; P < 4; P++) {
                const uint32_t vo = (uint32_t)((16 * s + klaneV) * ROWH + 16 * P + nlaneV) * 2;
                uint32_t vb[4];
                LDSM4T(vb, vh + vo);
                MMA16816(ctx[2 * P],     phi, vb[0], vb[1]);
                MMA16816(ctx[2 * P + 1], phi, vb[2], vb[3]);
                MMA16816(ctx[2 * P],     plo, vb[0], vb[1]);
                MMA16816(ctx[2 * P + 1], plo, vb[2], vb[3]);
            }
        }
        __syncthreads();
    }

    // ---- zinv + ctx epilogue ----
    z0 += __shfl_xor_sync(0xffffffffu, z0, 1);
    z0 += __shfl_xor_sync(0xffffffffu, z0, 2);
    z1 += __shfl_xor_sync(0xffffffffu, z1, 1);
    z1 += __shfl_xor_sync(0xffffffffu, z1, 2);
    const float zinv0 = 1.0f / z0, zinv1 = 1.0f / z1;
    if (qc == 0) {
        g_zinv[bh * S_ + gr0] = zinv0;
        g_zinv[bh * S_ + gr1] = zinv1;
    }

    float* crow0 = ctx_out + (bh * S_ + gr0) * DK_;
    float* crow1 = ctx_out + (bh * S_ + gr1) * DK_;
    #pragma unroll
    for (int j = 0; j < 8; j++) {
        const int col = 8 * j + 2 * qc;
        __stwt((float2*)(crow0 + col), make_float2(ctx[j][0] * zinv0, ctx[j][1] * zinv0));
        __stwt((float2*)(crow1 + col), make_float2(ctx[j][2] * zinv1, ctx[j][3] * zinv1));
    }
}

// ================= norm: e.fp16 -> attn.fp32 (pure streaming) =================
__global__ void __launch_bounds__(256)
norm_kernel(float* __restrict__ attn_out)
{
    const size_t row = blockIdx.x;               // B*H*S rows
    const float zi = g_zinv[row];
    const uint4* e = (const uint4*)(g_escr + row * (size_t)S_);
    float4* a = (float4*)(attn_out + row * (size_t)S_);
    const int t = threadIdx.x;
    uint4 v = __ldcs(e + t);                     // 8 halves
    float2 p0 = unpack2(v.x), p1 = unpack2(v.y), p2 = unpack2(v.z), p3 = unpack2(v.w);
    __stwt(a + 2 * t,     make_float4(p0.x * zi, p0.y * zi, p1.x * zi, p1.y * zi));
    __stwt(a + 2 * t + 1, make_float4(p2.x * zi, p2.y * zi, p3.x * zi, p3.y * zi));
}

// ---------------- launch ----------------
extern "C" void kernel_launch(void* const* d_in, const int* in_sizes, int n_in,
                              void* d_out, int out_size) {
    (void)in_sizes; (void)n_in; (void)out_size;
    const float* Q = (const float*)d_in[0];
    const float* K = (const float*)d_in[1];
    const float* V = (const float*)d_in[2];
    const void*  mask = d_in[3];

    float* ctx_out  = (float*)d_out;
    float* attn_out = ctx_out + NEL;

    cudaFuncSetAttribute(attn_main, cudaFuncAttributeMaxDynamicSharedMemorySize, SMEM_BYTES);

    prep_kernel<<<1024, 256>>>((const float4*)Q, (const float4*)K, (const float4*)V,
                               (const unsigned int*)mask);
    dim3 grid(S_ / MT, H_, B_);
    attn_main<<<grid, NTHR, SMEM_BYTES>>>(ctx_out);
    norm_kernel<<<B_ * H_ * S_, 256>>>(attn_out);
}

// round 8
// speedup vs baseline: 1.7574x; 1.1482x over previous
#include <cuda_runtime.h>
#include <cuda_fp16.h>
#include <stdint.h>

#define B_  4
#define H_  16
#define S_  2048
#define DK_ 64
#define MT  128     // q rows per CTA
#define KT  128     // k rows per smem tile (computed in two 64-col halves)
#define NTHR 256    // 8 warps, 16 q-rows each
#define ROWH 72     // padded row pitch in halves (144B)

// ---------------- static scratch ----------------
#define NEL ((size_t)B_ * H_ * S_ * DK_)            // 8.4M
__device__ __align__(16) __half g_qh[NEL], g_ql[NEL];
__device__ __align__(16) __half g_kh[NEL];
__device__ __align__(16) __half g_vh[NEL];
__device__ __align__(16) __half g_escr[(size_t)B_ * H_ * S_ * S_];     // 512MB unnormalized e (fp16)
__device__ __align__(16) unsigned long long g_maskbits[(size_t)B_ * S_ * (S_ / 64)];
__device__ float g_zinv[B_ * H_ * S_];

// ---------------- helpers ----------------
__device__ __forceinline__ uint32_t pack2(float a, float b) {
    __half2 h = __floats2half2_rn(a, b);
    return *reinterpret_cast<uint32_t*>(&h);
}
__device__ __forceinline__ float2 unpack2(uint32_t u) {
    __half2 h = *reinterpret_cast<__half2*>(&u);
    return __half22float2(h);
}
__device__ __forceinline__ void cp16(uint32_t dst, const void* src) {
    asm volatile("cp.async.cg.shared.global [%0], [%1], 16;" :: "r"(dst), "l"(src));
}
#define CP_COMMIT() asm volatile("cp.async.commit_group;" ::: "memory")
#define CP_WAIT1()  asm volatile("cp.async.wait_group 1;" ::: "memory")

#define LDSM4(r, a) \
    asm volatile("ldmatrix.sync.aligned.m8n8.x4.shared.b16 {%0,%1,%2,%3}, [%4];" \
        : "=r"((r)[0]), "=r"((r)[1]), "=r"((r)[2]), "=r"((r)[3]) : "r"(a))
#define LDSM4T(r, a) \
    asm volatile("ldmatrix.sync.aligned.m8n8.x4.trans.shared.b16 {%0,%1,%2,%3}, [%4];" \
        : "=r"((r)[0]), "=r"((r)[1]), "=r"((r)[2]), "=r"((r)[3]) : "r"(a))
#define MMA16816(c, a, b0, b1) \
    asm volatile("mma.sync.aligned.m16n8k16.row.col.f32.f16.f16.f32 " \
        "{%0,%1,%2,%3},{%4,%5,%6,%7},{%8,%9},{%0,%1,%2,%3};" \
        : "+f"((c)[0]), "+f"((c)[1]), "+f"((c)[2]), "+f"((c)[3]) \
        : "r"((a)[0]), "r"((a)[1]), "r"((a)[2]), "r"((a)[3]), "r"(b0), "r"(b1))

// smem layout in halves: Qh | Ql | 2 x {Kh[128][72], Vh[128][72]}
#define OFF_QH 0
#define OFF_QL 9216
#define OFF_BUF 18432
#define BUF_SZ  18432      // per buffer: Kh 9216 + Vh 9216 halves
#define SMEM_BYTES ((OFF_BUF + 2 * BUF_SZ) * 2)    // 110592 B

// ================= prep: Q -> fp16 hi/lo (x0.125), K/V -> fp16, mask -> bits ==========
__global__ void prep_kernel(const float4* __restrict__ Q, const float4* __restrict__ K,
                            const float4* __restrict__ V, const unsigned int* __restrict__ m)
{
    const int tid = threadIdx.x;
    if (blockIdx.x < 512) {
        const size_t n = NEL / 4;
        for (size_t i = (size_t)blockIdx.x * 256 + tid; i < n; i += 512 * 256) {
            float4 q = Q[i];
            q.x *= 0.125f; q.y *= 0.125f; q.z *= 0.125f; q.w *= 0.125f;
            uint32_t h0 = pack2(q.x, q.y), h1 = pack2(q.z, q.w);
            float2 a0 = unpack2(h0), a1 = unpack2(h1);
            *(uint2*)(g_qh + 4 * i) = make_uint2(h0, h1);
            *(uint2*)(g_ql + 4 * i) = make_uint2(pack2(q.x - a0.x, q.y - a0.y),
                                                 pack2(q.z - a1.x, q.w - a1.y));
            float4 k = K[i];
            *(uint2*)(g_kh + 4 * i) = make_uint2(pack2(k.x, k.y), pack2(k.z, k.w));
            float4 v = V[i];
            *(uint2*)(g_vh + 4 * i) = make_uint2(pack2(v.x, v.y), pack2(v.z, v.w));
        }
    } else {
        __shared__ int bad01_s, isfloat_s;
        if (tid == 0) { bad01_s = 0; isfloat_s = 1; }
        __syncthreads();
        int bad01 = 0;
        for (int i = tid; i < 4096; i += 256)
            if (m[i] > 1u) bad01 = 1;
        if (bad01) atomicExch(&bad01_s, 1);
        __syncthreads();
        if (bad01_s) {
            int notf = 0;
            for (int i = tid; i < 4096; i += 256) {
                unsigned v = m[i];
                if (v != 0u && v != 0x3F800000u) notf = 1;
            }
            if (notf) atomicExch(&isfloat_s, 0);
        }
        __syncthreads();
        const bool bytemask = bad01_s && !isfloat_s;
        const size_t n = (size_t)B_ * S_ * (S_ / 64);
        for (size_t i = (size_t)(blockIdx.x - 512) * 256 + tid; i < n; i += 512 * 256) {
            unsigned long long bits = 0ull;
            if (bytemask) {
                const uint4* p = (const uint4*)((const unsigned char*)m + i * 64);
                #pragma unroll
                for (int j = 0; j < 4; j++) {
                    uint4 v = p[j];
                    unsigned w[4] = {v.x, v.y, v.z, v.w};
                    #pragma unroll
                    for (int q = 0; q < 4; q++)
                        #pragma unroll
                        for (int bb = 0; bb < 4; bb++)
                            bits |= (unsigned long long)(((w[q] >> (8 * bb)) & 0xffu) == 0u)
                                    << (j * 16 + q * 4 + bb);
                }
            } else {
                const uint4* p = (const uint4*)m + i * 16;
                #pragma unroll
                for (int j = 0; j < 16; j++) {
                    uint4 v = p[j];
                    bits |= ((unsigned long long)(v.x == 0u) << (4 * j))
                          | ((unsigned long long)(v.y == 0u) << (4 * j + 1))
                          | ((unsigned long long)(v.z == 0u) << (4 * j + 2))
                          | ((unsigned long long)(v.w == 0u) << (4 * j + 3));
                }
            }
            g_maskbits[i] = bits;
        }
    }
}

// ================= mainloop: flash -> ctx + zinv + e.fp16 scratch =================
__global__ void __launch_bounds__(NTHR, 1)
attn_main(float* __restrict__ ctx_out)
{
    extern __shared__ __half shm[];
    const uint32_t sb = (uint32_t)__cvta_generic_to_shared(shm);

    const int tid = threadIdx.x, wid = tid >> 5, lane = tid & 31;
    const int r = lane >> 2, qc = lane & 3;
    const int m0 = 16 * wid;
    const int arow = lane & 15;
    const int akof = (lane >> 4) << 3;
    const int nlaneK = (lane & 7) + ((lane & 16) >> 1);
    const int klaneK = lane & 8;
    const int klaneV = lane & 15;
    const int nlaneV = (lane >> 4) << 3;

    const int q0 = blockIdx.x * MT;
    const size_t bh = (size_t)blockIdx.z * H_ + blockIdx.y;
    const size_t kvbase = bh * S_ * DK_;

    const int gr0 = q0 + m0 + r, gr1 = gr0 + 8;
    const unsigned long long* mbp = g_maskbits + (size_t)blockIdx.z * S_ * (S_ / 64);
    const __half* kvsrc[2] = {g_kh + kvbase, g_vh + kvbase};
    __half* ep0 = g_escr + (bh * S_ + gr0) * (size_t)S_;
    __half* ep1 = g_escr + (bh * S_ + gr1) * (size_t)S_;

    // ---- issue Q + tile 0 loads ----
    {
        const size_t qrow0 = bh * S_ + q0;
        #pragma unroll
        for (int it = 0; it < 8; it++) {
            int i = tid + it * NTHR;           // 0..2047: Qh then Ql
            int arr = i >> 10, rem = i & 1023, row = rem >> 3, c8 = rem & 7;
            const __half* src = (arr ? g_ql : g_qh) + (qrow0 + row) * DK_ + c8 * 8;
            cp16(sb + ((arr ? OFF_QL : OFF_QH) + row * ROWH + c8 * 8) * 2, src);
        }
        #pragma unroll
        for (int it = 0; it < 8; it++) {
            int i = tid + it * NTHR;           // 0..2047: {Kh,Vh} x 128 rows x 8 chunks
            int arr = i >> 10, rem = i & 1023, row = rem >> 3, c8 = rem & 7;
            cp16(sb + (OFF_BUF + arr * 9216 + row * ROWH + c8 * 8) * 2,
                 kvsrc[arr] + (size_t)row * DK_ + c8 * 8);
        }
        CP_COMMIT();
    }

    float ctx[8][4];
    #pragma unroll
    for (int j = 0; j < 8; j++)
        #pragma unroll
        for (int k = 0; k < 4; k++) ctx[j][k] = 0.f;
    float z0 = 0.f, z1 = 0.f;

    uint32_t qhi[4][4], qlo[4][4];
    bool qloaded = false;

    for (int kt = 0; kt < S_ / KT; kt++) {
        if (kt < S_ / KT - 1) {
            const int nb = OFF_BUF + ((kt + 1) & 1) * BUF_SZ;
            const size_t rbase = (size_t)(kt + 1) * KT * DK_;
            #pragma unroll
            for (int it = 0; it < 8; it++) {
                int i = tid + it * NTHR;
                int arr = i >> 10, rem = i & 1023, row = rem >> 3, c8 = rem & 7;
                cp16(sb + (nb + arr * 9216 + row * ROWH + c8 * 8) * 2,
                     kvsrc[arr] + rbase + (size_t)row * DK_ + c8 * 8);
            }
        }
        CP_COMMIT();
        CP_WAIT1();
        __syncthreads();

        if (!qloaded) {
            qloaded = true;
            #pragma unroll
            for (int s = 0; s < 4; s++) {
                const uint32_t qa = (uint32_t)((m0 + arow) * ROWH + 16 * s + akof) * 2;
                LDSM4(qhi[s], sb + OFF_QH * 2 + qa);
                LDSM4(qlo[s], sb + OFF_QL * 2 + qa);
            }
        }

        const int bufb = OFF_BUF + (kt & 1) * BUF_SZ;
        const uint32_t kh = sb + bufb * 2;
        const uint32_t vh = sb + (bufb + 9216) * 2;

        #pragma unroll
        for (int half = 0; half < 2; half++) {
            const int rowoff = half * 64;

            // ---- GEMM1: 16x64 scores = (Qhi + Qlo) * Khi[rowoff..rowoff+64) ----
            float c[8][4];
            #pragma unroll
            for (int j = 0; j < 8; j++)
                #pragma unroll
                for (int k = 0; k < 4; k++) c[j][k] = 0.f;

            #pragma unroll
            for (int s = 0; s < 4; s++) {
                #pragma unroll
                for (int Jp = 0; Jp < 4; Jp++) {
                    const uint32_t bo =
                        (uint32_t)((rowoff + 16 * Jp + nlaneK) * ROWH + 16 * s + klaneK) * 2;
                    uint32_t kb[4];
                    LDSM4(kb, kh + bo);
                    MMA16816(c[2 * Jp],     qhi[s], kb[0], kb[1]);
                    MMA16816(c[2 * Jp + 1], qhi[s], kb[2], kb[3]);
                    MMA16816(c[2 * Jp],     qlo[s], kb[0], kb[1]);
                    MMA16816(c[2 * Jp + 1], qlo[s], kb[2], kb[3]);
                }
            }

            // ---- elt + single-term GEMM2 per k16-chunk ----
            const int mwi = 2 * kt + half;
            const unsigned long long mw0 = mbp[(size_t)gr0 * (S_ / 64) + mwi];
            const unsigned long long mw1 = mbp[(size_t)gr1 * (S_ / 64) + mwi];
            const int colbase = kt * KT + rowoff;

            #pragma unroll
            for (int s = 0; s < 4; s++) {
                uint32_t phi[4];
                #pragma unroll
                for (int jj = 0; jj < 2; jj++) {
                    const int j = 2 * s + jj;
                    const int col = 8 * j + 2 * qc;
                    float e00 = ((mw0 >> col) & 1ull)       ? __expf(c[j][0]) : 0.f;
                    float e01 = ((mw0 >> (col + 1)) & 1ull) ? __expf(c[j][1]) : 0.f;
                    float e10 = ((mw1 >> col) & 1ull)       ? __expf(c[j][2]) : 0.f;
                    float e11 = ((mw1 >> (col + 1)) & 1ull) ? __expf(c[j][3]) : 0.f;
                    z0 += e00 + e01; z1 += e10 + e11;
                    uint32_t h0 = pack2(e00, e01), h1 = pack2(e10, e11);
                    __stwt((uint32_t*)((char*)ep0 + (size_t)(colbase + col) * 2), h0);
                    __stwt((uint32_t*)((char*)ep1 + (size_t)(colbase + col) * 2), h1);
                    phi[2 * jj] = h0; phi[2 * jj + 1] = h1;
                }
                #pragma unroll
                for (int P = 0; P < 4; P++) {
                    const uint32_t vo =
                        (uint32_t)((rowoff + 16 * s + klaneV) * ROWH + 16 * P + nlaneV) * 2;
                    uint32_t vb[4];
                    LDSM4T(vb, vh + vo);
                    MMA16816(ctx[2 * P],     phi, vb[0], vb[1]);
                    MMA16816(ctx[2 * P + 1], phi, vb[2], vb[3]);
                }
            }
        }
        __syncthreads();
    }

    // ---- zinv + ctx epilogue ----
    z0 += __shfl_xor_sync(0xffffffffu, z0, 1);
    z0 += __shfl_xor_sync(0xffffffffu, z0, 2);
    z1 += __shfl_xor_sync(0xffffffffu, z1, 1);
    z1 += __shfl_xor_sync(0xffffffffu, z1, 2);
    const float zinv0 = 1.0f / z0, zinv1 = 1.0f / z1;
    if (qc == 0) {
        g_zinv[bh * S_ + gr0] = zinv0;
        g_zinv[bh * S_ + gr1] = zinv1;
    }

    float* crow0 = ctx_out + (bh * S_ + gr0) * DK_;
    float* crow1 = ctx_out + (bh * S_ + gr1) * DK_;
    #pragma unroll
    for (int j = 0; j < 8; j++) {
        const int col = 8 * j + 2 * qc;
        __stwt((float2*)(crow0 + col), make_float2(ctx[j][0] * zinv0, ctx[j][1] * zinv0));
        __stwt((float2*)(crow1 + col), make_float2(ctx[j][2] * zinv1, ctx[j][3] * zinv1));
    }
}

// ================= norm: e.fp16 -> attn.fp32 (pure streaming) =================
__global__ void __launch_bounds__(256)
norm_kernel(float* __restrict__ attn_out)
{
    const size_t row = blockIdx.x;               // B*H*S rows
    const float zi = g_zinv[row];
    const uint4* e = (const uint4*)(g_escr + row * (size_t)S_);
    float4* a = (float4*)(attn_out + row * (size_t)S_);
    const int t = threadIdx.x;
    uint4 v = __ldcs(e + t);                     // 8 halves
    float2 p0 = unpack2(v.x), p1 = unpack2(v.y), p2 = unpack2(v.z), p3 = unpack2(v.w);
    __stwt(a + 2 * t,     make_float4(p0.x * zi, p0.y * zi, p1.x * zi, p1.y * zi));
    __stwt(a + 2 * t + 1, make_float4(p2.x * zi, p2.y * zi, p3.x * zi, p3.y * zi));
}

// ---------------- launch ----------------
extern "C" void kernel_launch(void* const* d_in, const int* in_sizes, int n_in,
                              void* d_out, int out_size) {
    (void)in_sizes; (void)n_in; (void)out_size;
    const float* Q = (const float*)d_in[0];
    const float* K = (const float*)d_in[1];
    const float* V = (const float*)d_in[2];
    const void*  mask = d_in[3];

    float* ctx_out  = (float*)d_out;
    float* attn_out = ctx_out + NEL;

    cudaFuncSetAttribute(attn_main, cudaFuncAttributeMaxDynamicSharedMemorySize, SMEM_BYTES);

    prep_kernel<<<1024, 256>>>((const float4*)Q, (const float4*)K, (const float4*)V,
                               (const unsigned int*)mask);
    dim3 grid(S_ / MT, H_, B_);
    attn_main<<<grid, NTHR, SMEM_BYTES>>>(ctx_out);
    norm_kernel<<<B_ * H_ * S_, 256>>>(attn_out);
}